// round 4
// baseline (speedup 1.0000x reference)
#include <cuda_runtime.h>

// LayerwiseLowRankUplift: out = z + U_l (V_l^T z), grouped by layer.
// B=2048, H=2048, R=64, NL=32. fp32 grouped-GEMM, FMA-bound tiling.

constexpr int B  = 2048;
constexpr int H  = 2048;
constexpr int R  = 64;
constexpr int NL = 32;

constexpr int TS     = 32;          // samples per tile
constexpr int ST     = 4;           // sample-tile grid extent (grid-strided beyond)
constexpr int KPART  = 8;           // split-K factor for pass 1
constexpr int KSLICE = H / KPART;   // 256
constexpr int HTILE  = 128;         // h per tile in pass 2

// ---------------- device scratch (no allocation allowed) ----------------
__device__ int d_offset[NL + 1];
__device__ int d_order[B];
__device__ __align__(16) float d_projp[(size_t)KPART * B * R];  // 4 MB partials

// ---------------- single fused grouping kernel (1 block) ----------------
// Slot order within a layer is atomic-race dependent, but each sample's math
// depends only on its own slot contents -> output is bitwise deterministic.
__global__ void k_group(const int* __restrict__ lid) {
    __shared__ int cnt[NL], off[NL], cur[NL];
    const int t = threadIdx.x;
    if (t < NL) { cnt[t] = 0; cur[t] = 0; }
    __syncthreads();
    int myl[B / 256];
    #pragma unroll
    for (int j = 0; j < B / 256; j++) {
        myl[j] = lid[t + j * 256];
        atomicAdd(&cnt[myl[j]], 1);
    }
    __syncthreads();
    if (t == 0) {
        int acc = 0;
        for (int l = 0; l < NL; l++) { off[l] = acc; d_offset[l] = acc; acc += cnt[l]; }
        d_offset[NL] = acc;
    }
    __syncthreads();
    #pragma unroll
    for (int j = 0; j < B / 256; j++) {
        int l = myl[j];
        int pos = off[l] + atomicAdd(&cur[l], 1);
        d_order[pos] = t + j * 256;
    }
}

// ---------------- pass 1: proj_part[kp][slot][r] = sum_{h in slice} v[l][h][r] * z[b][h]
// 128 threads. micro-tile 2 samples x 8 r. FMA-bound (2.5 B/FMA crossbar).
__global__ __launch_bounds__(128) void k_pass1(const float* __restrict__ z,
                                               const float* __restrict__ v) {
    const int l     = blockIdx.z;
    const int kpart = blockIdx.y;
    const int start = d_offset[l];
    const int cnt   = d_offset[l + 1] - start;
    const int t     = threadIdx.x;
    const int sidx  = t & 15;   // 16 groups x 2 samples
    const int ridx  = t >> 4;   // 8 groups x 8 r
    const int kbase = kpart * KSLICE;

    __shared__ __align__(16) float zs[32][34];   // [k][s]
    __shared__ __align__(16) float vs[32][68];   // [k][r]
    __shared__ int ord[TS];

    for (int s0 = blockIdx.x * TS; s0 < cnt; s0 += ST * TS) {
        if (t < TS) ord[t] = (s0 + t < cnt) ? d_order[start + s0 + t] : -1;
        __syncthreads();

        float acc[2][8] = {};

        for (int kk = 0; kk < KSLICE; kk += 32) {
            // z tile (gathered rows) -> [k][s], coalesced per sample row
            #pragma unroll
            for (int i = 0; i < 8; i++) {
                int idx = t + i * 128;
                int k = idx & 31, s = idx >> 5;
                int b = ord[s];
                zs[k][s] = (b >= 0) ? z[(size_t)b * H + kbase + kk + k] : 0.f;
            }
            // v tile [k][r], float4 coalesced
            #pragma unroll
            for (int i = 0; i < 4; i++) {
                int f = t + i * 128;
                int c = f & 15, k = f >> 4;
                float4 val = *(const float4*)&v[((size_t)l * H + kbase + kk + k) * R + 4 * c];
                *(float4*)&vs[k][4 * c] = val;
            }
            __syncthreads();

            #pragma unroll
            for (int k = 0; k < 32; k++) {
                float2 zf  = *(const float2*)&zs[k][2 * sidx];
                float4 vf0 = *(const float4*)&vs[k][8 * ridx];
                float4 vf1 = *(const float4*)&vs[k][8 * ridx + 4];
                acc[0][0] += zf.x * vf0.x; acc[0][1] += zf.x * vf0.y;
                acc[0][2] += zf.x * vf0.z; acc[0][3] += zf.x * vf0.w;
                acc[0][4] += zf.x * vf1.x; acc[0][5] += zf.x * vf1.y;
                acc[0][6] += zf.x * vf1.z; acc[0][7] += zf.x * vf1.w;
                acc[1][0] += zf.y * vf0.x; acc[1][1] += zf.y * vf0.y;
                acc[1][2] += zf.y * vf0.z; acc[1][3] += zf.y * vf0.w;
                acc[1][4] += zf.y * vf1.x; acc[1][5] += zf.y * vf1.y;
                acc[1][6] += zf.y * vf1.z; acc[1][7] += zf.y * vf1.w;
            }
            __syncthreads();
        }

        #pragma unroll
        for (int i = 0; i < 2; i++) {
            int s = 2 * sidx + i;
            if (s0 + s < cnt) {
                size_t base = ((size_t)kpart * B + (start + s0 + s)) * R + 8 * ridx;
                *(float4*)&d_projp[base]     = make_float4(acc[i][0], acc[i][1], acc[i][2], acc[i][3]);
                *(float4*)&d_projp[base + 4] = make_float4(acc[i][4], acc[i][5], acc[i][6], acc[i][7]);
            }
        }
    }
}

// ---------------- pass 2: out[b][h] = z[b][h] + sum_r u[l][h][r] * proj[slot][r]
// 256 threads, micro-tile 4 samples x 4 h, r vectorized by float4. FMA-bound.
__global__ __launch_bounds__(256) void k_pass2(const float* __restrict__ z,
                                               const float* __restrict__ u,
                                               float* __restrict__ out) {
    const int l     = blockIdx.z;
    const int start = d_offset[l];
    const int cnt   = d_offset[l + 1] - start;
    if (cnt == 0) return;
    const int h0   = blockIdx.x * HTILE;
    const int t    = threadIdx.x;
    const int sidx = t & 7;    // 8 groups x 4 samples
    const int hidx = t >> 3;   // 32 groups x 4 h

    __shared__ __align__(16) float ps[TS][68];      // [s][r]
    __shared__ __align__(16) float us[HTILE][68];   // [h][r]
    __shared__ int ord[TS];

    // u tile once per block
    #pragma unroll
    for (int i = 0; i < 8; i++) {
        int f = t + i * 256;              // 128 rows x 16 float4
        int h = f >> 4, c = f & 15;
        float4 val = *(const float4*)&u[((size_t)l * H + h0 + h) * R + 4 * c];
        *(float4*)&us[h][4 * c] = val;
    }

    for (int s0 = blockIdx.y * TS; s0 < cnt; s0 += ST * TS) {
        if (t < TS) ord[t] = (s0 + t < cnt) ? d_order[start + s0 + t] : -1;
        // proj tile: sum KPART split-K partials in fixed order (deterministic)
        #pragma unroll
        for (int i = 0; i < 2; i++) {
            int f = t + i * 256;          // 32 rows x 16 float4
            int s = f >> 4, c = f & 15;
            float4 val = make_float4(0.f, 0.f, 0.f, 0.f);
            if (s0 + s < cnt) {
                size_t slot = (size_t)(start + s0 + s);
                #pragma unroll
                for (int kp = 0; kp < KPART; kp++) {
                    float4 p = *(const float4*)&d_projp[((size_t)kp * B + slot) * R + 4 * c];
                    val.x += p.x; val.y += p.y; val.z += p.z; val.w += p.w;
                }
            }
            *(float4*)&ps[s][4 * c] = val;
        }
        __syncthreads();

        float acc[4][4] = {};
        #pragma unroll
        for (int r = 0; r < R; r += 4) {
            float4 pv[4], uv[4];
            #pragma unroll
            for (int i = 0; i < 4; i++) pv[i] = *(const float4*)&ps[4 * sidx + i][r];
            #pragma unroll
            for (int j = 0; j < 4; j++) uv[j] = *(const float4*)&us[4 * hidx + j][r];
            #pragma unroll
            for (int i = 0; i < 4; i++)
                #pragma unroll
                for (int j = 0; j < 4; j++)
                    acc[i][j] += pv[i].x * uv[j].x + pv[i].y * uv[j].y
                               + pv[i].z * uv[j].z + pv[i].w * uv[j].w;
        }

        // epilogue: out = z + delta
        #pragma unroll
        for (int i = 0; i < 4; i++) {
            int s = 4 * sidx + i;
            int b = ord[s];
            if (b >= 0) {
                size_t off = (size_t)b * H + h0 + 4 * hidx;
                float4 zv = *(const float4*)&z[off];
                *(float4*)&out[off] = make_float4(zv.x + acc[i][0], zv.y + acc[i][1],
                                                  zv.z + acc[i][2], zv.w + acc[i][3]);
            }
        }
        __syncthreads();  // protect ps/ord before next stile
    }
}

// ---------------- launcher ----------------
extern "C" void kernel_launch(void* const* d_in, const int* in_sizes, int n_in,
                              void* d_out, int out_size) {
    const float* z   = (const float*)d_in[0];
    const int*   lid = (const int*)d_in[1];
    const float* u   = (const float*)d_in[2];
    const float* v   = (const float*)d_in[3];
    float* out = (float*)d_out;

    k_group<<<1, 256>>>(lid);
    k_pass1<<<dim3(ST, KPART, NL), 128>>>(z, v);
    k_pass2<<<dim3(H / HTILE, ST, NL), 256>>>(z, u, out);
}

// round 9
// speedup vs baseline: 2.0006x; 2.0006x over previous
#include <cuda_runtime.h>

// LayerwiseLowRankUplift: out = z + U_l (V_l^T z), grouped by layer.
// B=2048, H=2048, R=64, NL=32. tf32 mma.sync grouped-GEMM formulation.

constexpr int B  = 2048;
constexpr int H  = 2048;
constexpr int R  = 64;
constexpr int NL = 32;

constexpr int KPART  = 8;           // split-K for pass 1
constexpr int KSLICE = H / KPART;   // 256
constexpr int KCHUNK = 64;          // k per smem stage in pass 1
constexpr int HTILE2 = 128;         // h per block in pass 2

// ---------------- device scratch ----------------
__device__ int d_offset[NL + 1];
__device__ int d_order[B];
__device__ __align__(16) float d_projp[(size_t)KPART * B * R];  // 4 MB partials

// ---------------- tf32 MMA helper ----------------
__device__ __forceinline__ void mma_tf32(float* d, float a0, float a1, float a2, float a3,
                                         float b0, float b1) {
    asm volatile(
        "mma.sync.aligned.m16n8k8.row.col.f32.tf32.tf32.f32 "
        "{%0,%1,%2,%3}, {%4,%5,%6,%7}, {%8,%9}, {%0,%1,%2,%3};\n"
        : "+f"(d[0]), "+f"(d[1]), "+f"(d[2]), "+f"(d[3])
        : "r"(__float_as_uint(a0)), "r"(__float_as_uint(a1)),
          "r"(__float_as_uint(a2)), "r"(__float_as_uint(a3)),
          "r"(__float_as_uint(b0)), "r"(__float_as_uint(b1)));
}

// ---------------- grouping: warp-aggregated counting sort ----------------
// Slot order within a layer is atomic-race dependent, but every sample's math
// depends only on its own row -> output is bitwise deterministic.
__global__ void k_group(const int* __restrict__ lid) {
    __shared__ int cnt[NL], off[NL], cur[NL];
    const int t = threadIdx.x, lane = t & 31;
    if (t < NL) { cnt[t] = 0; cur[t] = 0; }
    __syncthreads();
    int myl[B / 256];
    #pragma unroll
    for (int j = 0; j < B / 256; j++) myl[j] = lid[t + j * 256];
    #pragma unroll
    for (int j = 0; j < B / 256; j++) {
        unsigned m = __match_any_sync(0xffffffffu, myl[j]);
        if (lane == __ffs(m) - 1) atomicAdd(&cnt[myl[j]], __popc(m));
    }
    __syncthreads();
    if (t == 0) {
        int acc = 0;
        for (int l = 0; l < NL; l++) { off[l] = acc; d_offset[l] = acc; acc += cnt[l]; }
        d_offset[NL] = acc;
    }
    __syncthreads();
    #pragma unroll
    for (int j = 0; j < B / 256; j++) {
        unsigned m = __match_any_sync(0xffffffffu, myl[j]);
        int leader = __ffs(m) - 1;
        int base = 0;
        if (lane == leader) base = atomicAdd(&cur[myl[j]], __popc(m));
        base = __shfl_sync(m, base, leader);
        int pos = off[myl[j]] + base + __popc(m & ((1u << lane) - 1));
        d_order[pos] = t + j * 256;
    }
}

// ---------------- pass 1: proj_part[kp][slot][:] = V_l[slice]^T z[slot][slice] ----------------
// Block: (kp, l). Tile M=64 samples x N=64 r x K=256. 8 warps as 4m x 2n.
__global__ __launch_bounds__(256) void k_pass1(const float* __restrict__ z,
                                               const float* __restrict__ v) {
    const int l = blockIdx.y, kp = blockIdx.x;
    const int start = d_offset[l], cnt = d_offset[l + 1] - start;
    if (cnt == 0) return;
    const int t = threadIdx.x, w = t >> 5, lane = t & 31;
    const int m0 = (w & 3) * 16, n0 = (w >> 2) * 32;
    const int kbase = kp * KSLICE;
    const int row = t >> 2, q = t & 3;

    __shared__ float zs[64 * 64];   // [s][k], A-swizzle: col ^ ((row&7)<<2)
    __shared__ float vs[64 * 64];   // [k][r], B-swizzle: col ^ ((row&3)<<3)
    __shared__ int ord[64];

    for (int s0 = 0; s0 < cnt; s0 += 64) {
        if (t < 64) ord[t] = (s0 + t < cnt) ? d_order[start + s0 + t] : -1;
        __syncthreads();
        float acc[4][4] = {};

        for (int kc = 0; kc < KSLICE; kc += KCHUNK) {
            const int b = ord[row];
            #pragma unroll
            for (int j = 0; j < 4; j++) {
                int col = q * 4 + j * 16;
                float4 val = make_float4(0.f, 0.f, 0.f, 0.f);
                if (b >= 0) val = *(const float4*)&z[(size_t)b * H + kbase + kc + col];
                *(float4*)&zs[row * 64 + (col ^ ((row & 7) << 2))] = val;
            }
            #pragma unroll
            for (int j = 0; j < 4; j++) {
                int col = q * 4 + j * 16;
                float4 val = *(const float4*)&v[((size_t)l * H + kbase + kc + row) * R + col];
                *(float4*)&vs[row * 64 + (col ^ ((row & 3) << 3))] = val;
            }
            __syncthreads();

            #pragma unroll
            for (int ks = 0; ks < 8; ks++) {
                const int k0 = ks * 8;
                const int ar = m0 + (lane >> 2);
                const int ac = k0 + (lane & 3);
                const int sw = (ar & 7) << 2;          // same for ar and ar+8
                float a0 = zs[ar * 64 + (ac ^ sw)];
                float a1 = zs[(ar + 8) * 64 + (ac ^ sw)];
                float a2 = zs[ar * 64 + ((ac + 4) ^ sw)];
                float a3 = zs[(ar + 8) * 64 + ((ac + 4) ^ sw)];
                const int br = k0 + (lane & 3);
                const int bsw = (br & 3) << 3;         // same for br and br+4
                #pragma unroll
                for (int nt = 0; nt < 4; nt++) {
                    int bc = n0 + nt * 8 + (lane >> 2);
                    float b0 = vs[br * 64 + (bc ^ bsw)];
                    float b1 = vs[(br + 4) * 64 + (bc ^ bsw)];
                    mma_tf32(acc[nt], a0, a1, a2, a3, b0, b1);
                }
            }
            __syncthreads();
        }

        // store partial proj: d0,d1 -> row m; d2,d3 -> row m+8
        #pragma unroll
        for (int nt = 0; nt < 4; nt++) {
            int col = n0 + nt * 8 + 2 * (lane & 3);
            int sA = s0 + m0 + (lane >> 2);
            if (sA < cnt)
                *(float2*)&d_projp[((size_t)kp * B + (start + sA)) * R + col] =
                    make_float2(acc[nt][0], acc[nt][1]);
            if (sA + 8 < cnt)
                *(float2*)&d_projp[((size_t)kp * B + (start + sA + 8)) * R + col] =
                    make_float2(acc[nt][2], acc[nt][3]);
        }
        __syncthreads();
    }
}

// ---------------- pass 2: out[b][:] = z[b][:] + proj[slot] U_l[hchunk]^T ----------------
// Block: (hchunk, l). Tile M=64 samples x N=128 h x K=64 r. 8 warps as 2m x 4n.
__global__ __launch_bounds__(256) void k_pass2(const float* __restrict__ z,
                                               const float* __restrict__ u,
                                               float* __restrict__ out) {
    const int l = blockIdx.y;
    const int start = d_offset[l], cnt = d_offset[l + 1] - start;
    if (cnt == 0) return;
    const int h0 = blockIdx.x * HTILE2;
    const int t = threadIdx.x, w = t >> 5, lane = t & 31;
    const int m0 = (w & 1) * 32, n0 = (w >> 1) * 32;
    const int q = t & 3;

    __shared__ float us[HTILE2 * 64];  // [h][r], A-swizzle per h-row
    __shared__ float ps[64 * 64];      // [s][r], A-swizzle per s-row
    // total 48KB exactly

    // load u tile once (reused across sample stiles)
    #pragma unroll
    for (int i = 0; i < 2; i++) {
        int hrow = (t >> 2) + i * 64;
        #pragma unroll
        for (int j = 0; j < 4; j++) {
            int col = q * 4 + j * 16;
            float4 val = *(const float4*)&u[((size_t)l * H + h0 + hrow) * R + col];
            *(float4*)&us[hrow * 64 + (col ^ ((hrow & 7) << 2))] = val;
        }
    }

    for (int s0 = 0; s0 < cnt; s0 += 64) {
        // build proj tile = sum of KPART partials (fixed order -> deterministic)
        {
            const int srow = t >> 2;
            const int slot = start + s0 + srow;
            const bool valid = (s0 + srow) < cnt;
            #pragma unroll
            for (int j = 0; j < 4; j++) {
                int col = q * 4 + j * 16;
                float4 a4 = make_float4(0.f, 0.f, 0.f, 0.f);
                if (valid) {
                    #pragma unroll
                    for (int kp = 0; kp < KPART; kp++) {
                        float4 p = *(const float4*)&d_projp[((size_t)kp * B + slot) * R + col];
                        a4.x += p.x; a4.y += p.y; a4.z += p.z; a4.w += p.w;
                    }
                }
                *(float4*)&ps[srow * 64 + (col ^ ((srow & 7) << 2))] = a4;
            }
        }
        __syncthreads();

        float acc[2][4][4] = {};
        #pragma unroll
        for (int ks = 0; ks < 8; ks++) {
            const int k0 = ks * 8;
            float a[2][4];
            #pragma unroll
            for (int mi = 0; mi < 2; mi++) {
                int ar = m0 + mi * 16 + (lane >> 2);
                int ac = k0 + (lane & 3);
                int sw = (ar & 7) << 2;
                a[mi][0] = ps[ar * 64 + (ac ^ sw)];
                a[mi][1] = ps[(ar + 8) * 64 + (ac ^ sw)];
                a[mi][2] = ps[ar * 64 + ((ac + 4) ^ sw)];
                a[mi][3] = ps[(ar + 8) * 64 + ((ac + 4) ^ sw)];
            }
            #pragma unroll
            for (int nt = 0; nt < 4; nt++) {
                int hr = n0 + nt * 8 + (lane >> 2);
                int bk = k0 + (lane & 3);
                int sw = (hr & 7) << 2;
                float b0 = us[hr * 64 + (bk ^ sw)];
                float b1 = us[hr * 64 + ((bk + 4) ^ sw)];
                #pragma unroll
                for (int mi = 0; mi < 2; mi++)
                    mma_tf32(acc[mi][nt], a[mi][0], a[mi][1], a[mi][2], a[mi][3], b0, b1);
            }
        }

        // epilogue: out = z + delta (z added in full fp32)
        #pragma unroll
        for (int mi = 0; mi < 2; mi++) {
            int sr = s0 + m0 + mi * 16 + (lane >> 2);
            int bA = (sr < cnt) ? d_order[start + sr] : -1;
            int bB = (sr + 8 < cnt) ? d_order[start + sr + 8] : -1;
            #pragma unroll
            for (int nt = 0; nt < 4; nt++) {
                int hcol = h0 + n0 + nt * 8 + 2 * (lane & 3);
                if (bA >= 0) {
                    size_t off = (size_t)bA * H + hcol;
                    float2 zv = *(const float2*)&z[off];
                    *(float2*)&out[off] = make_float2(zv.x + acc[mi][nt][0],
                                                      zv.y + acc[mi][nt][1]);
                }
                if (bB >= 0) {
                    size_t off = (size_t)bB * H + hcol;
                    float2 zv = *(const float2*)&z[off];
                    *(float2*)&out[off] = make_float2(zv.x + acc[mi][nt][2],
                                                      zv.y + acc[mi][nt][3]);
                }
            }
        }
        __syncthreads();
    }
}

// ---------------- launcher ----------------
extern "C" void kernel_launch(void* const* d_in, const int* in_sizes, int n_in,
                              void* d_out, int out_size) {
    const float* z   = (const float*)d_in[0];
    const int*   lid = (const int*)d_in[1];
    const float* u   = (const float*)d_in[2];
    const float* v   = (const float*)d_in[3];
    float* out = (float*)d_out;

    k_group<<<1, 256>>>(lid);
    k_pass1<<<dim3(KPART, NL), 256>>>(z, v);
    k_pass2<<<dim3(H / HTILE2, NL), 256>>>(z, u, out);
}